// round 3
// baseline (speedup 1.0000x reference)
#include <cuda_runtime.h>

#define BB   8
#define NN   128
#define COOR 3
#define FF   128
#define FILT 128

// Scratch: A' = x @ w1 + bv  and  C = x @ w2, each [B, N, COOR, FILT]
__device__ float g_A[BB * NN * COOR * FILT];
__device__ float g_C[BB * NN * COOR * FILT];

// ---- packed f32x2 helpers (Blackwell FFMA2 path; per-lane IEEE f32) -------
typedef unsigned long long ull;

union F4U {
    float4 f4;
    ull    u[2];
};

__device__ __forceinline__ ull fma2(ull a, ull b, ull c) {
    ull r;
    asm("fma.rn.f32x2 %0, %1, %2, %3;" : "=l"(r) : "l"(a), "l"(b), "l"(c));
    return r;
}
__device__ __forceinline__ ull add2(ull a, ull b) {
    ull r;
    asm("add.rn.f32x2 %0, %1, %2;" : "=l"(r) : "l"(a), "l"(b));
    return r;
}
__device__ __forceinline__ ull mul2(ull a, ull b) {
    ull r;
    asm("mul.rn.f32x2 %0, %1, %2;" : "=l"(r) : "l"(a), "l"(b));
    return r;
}
__device__ __forceinline__ ull pack2(float lo, float hi) {
    ull r;
    asm("mov.b64 %0, {%1, %2};" : "=l"(r) : "r"(__float_as_uint(lo)), "r"(__float_as_uint(hi)));
    return r;
}

// ---------------------------------------------------------------------------
// Phase 1: tiny GEMM [3072, 128] @ [128, 256]  ->  g_A (with +bv), g_C
// Block = 128 thr (4 warps). Each warp covers ALL 128 k (4 k per lane, as
// two f32x2 pairs) for WR=2 rows -> 8 rows/block, 384 blocks.
// Per f per lane: 2x LDG.128 (w1,w2 quads) + 2 broadcast LDS + 8 fma2.
// ---------------------------------------------------------------------------
__global__ __launch_bounds__(128) void phase1_kernel(
    const float* __restrict__ x,   // [3072, 128]
    const float* __restrict__ w,   // [256, 128]
    const float* __restrict__ bv)  // [128]
{
    constexpr int WR = 2;                 // rows per warp
    constexpr int BR = 8;                 // rows per block
    const int r0   = blockIdx.x * BR;
    const int warp = threadIdx.x >> 5;
    const int lane = threadIdx.x & 31;
    const int k    = lane * 4;

    __shared__ float xs[BR][FF];          // row-major: broadcast-friendly

    // Coalesced load of 8 contiguous x rows.
    {
        const float4* xin = reinterpret_cast<const float4*>(x + (size_t)r0 * FF);
        float4* xs4 = reinterpret_cast<float4*>(&xs[0][0]);
        #pragma unroll
        for (int t = threadIdx.x; t < BR * FF / 4; t += 128) xs4[t] = xin[t];
    }
    __syncthreads();

    // acc[row][A/C][pair]
    ull acc[WR][2][2];
    {
        F4U bvq;
        bvq.f4 = *reinterpret_cast<const float4*>(bv + k);
        #pragma unroll
        for (int r = 0; r < WR; r++) {
            acc[r][0][0] = bvq.u[0];  acc[r][0][1] = bvq.u[1];
            acc[r][1][0] = 0ull;      acc[r][1][1] = 0ull;
        }
    }

    const float4* w1p = reinterpret_cast<const float4*>(w) + lane;
    const float4* w2p = reinterpret_cast<const float4*>(w + (size_t)FF * FILT) + lane;
    const int rbase = warp * WR;

    #pragma unroll 4
    for (int f = 0; f < FF; f++) {
        F4U w1; w1.f4 = w1p[f * (FILT / 4)];
        F4U w2; w2.f4 = w2p[f * (FILT / 4)];
        #pragma unroll
        for (int r = 0; r < WR; r++) {
            const float xv = xs[rbase + r][f];     // smem broadcast
            const ull xp = pack2(xv, xv);
            acc[r][0][0] = fma2(xp, w1.u[0], acc[r][0][0]);
            acc[r][0][1] = fma2(xp, w1.u[1], acc[r][0][1]);
            acc[r][1][0] = fma2(xp, w2.u[0], acc[r][1][0]);
            acc[r][1][1] = fma2(xp, w2.u[1], acc[r][1][1]);
        }
    }

    #pragma unroll
    for (int r = 0; r < WR; r++) {
        const size_t row = (size_t)(r0 + rbase + r);
        F4U oa; oa.u[0] = acc[r][0][0]; oa.u[1] = acc[r][0][1];
        F4U oc; oc.u[0] = acc[r][1][0]; oc.u[1] = acc[r][1][1];
        *reinterpret_cast<float4*>(&g_A[row * FILT + k]) = oa.f4;
        *reinterpret_cast<float4*>(&g_C[row * FILT + k]) = oc.f4;
    }
}

// ---------------------------------------------------------------------------
// Phase 2: out[b,i,j,k] = sum_c (A'[b,i,c,k] + C[b,j,c,k]) * d[b,i,j,c]
// Grid (NN/TI, JS, BB) = (32, 2, 8) = 512 blocks -> ~22+ warps/SM.
// Block (32,8): tx = k as float4, ty strides j within this block's j-half.
// Math in packed f32x2: 48 packed ops per j-iter instead of 96 scalar.
// ---------------------------------------------------------------------------
__global__ __launch_bounds__(256) void phase2_kernel(
    const float* __restrict__ dist,  // [B, N, N, COOR]
    float* __restrict__ out)         // [B, N, N, FILT]
{
    constexpr int TI = 4;
    constexpr int JS = 2;
    constexpr int JT = NN / JS;      // 64 j per block

    const int b  = blockIdx.z;
    const int i0 = blockIdx.x * TI;
    const int j0 = blockIdx.y * JT;
    const int tx = threadIdx.x;      // 0..31
    const int ty = threadIdx.y;      // 0..7
    const int tid = ty * 32 + tx;

    __shared__ float sd[TI * JT * COOR];   // 4*64*3 = 768 floats = 3 KB

    // Load distances slice d[b, i0:i0+4, j0:j0+64, :]. Each i-chunk is 192
    // contiguous floats (16B-aligned since j0*3 is a multiple of 4... j0=0 or 64 -> 0 or 192).
    {
        const float* dbase = dist + ((size_t)(b * NN + i0) * NN + j0) * COOR;
        #pragma unroll
        for (int t = tid; t < TI * JT * COOR / 4; t += 256) {
            const int e = t * 4;
            const int i = e / (JT * COOR);
            const int rem = e % (JT * COOR);
            reinterpret_cast<float4*>(sd)[t] =
                *reinterpret_cast<const float4*>(dbase + (size_t)i * NN * COOR + rem);
        }
    }

    // A' tile into registers (packed view).
    F4U Ar[TI][COOR];
    {
        const float4* A4 = reinterpret_cast<const float4*>(g_A);
        #pragma unroll
        for (int i = 0; i < TI; i++)
            #pragma unroll
            for (int c = 0; c < COOR; c++)
                Ar[i][c].f4 = A4[((size_t)(b * NN + i0 + i) * COOR + c) * (FILT / 4) + tx];
    }
    __syncthreads();

    const float4* C4 = reinterpret_cast<const float4*>(g_C) +
                       (size_t)b * NN * COOR * (FILT / 4) + tx;
    float4* out4 = reinterpret_cast<float4*>(out) +
                   ((size_t)(b * NN + i0) * NN + j0) * (FILT / 4) + tx;

    #pragma unroll 2
    for (int it = 0; it < JT / 8; it++) {
        const int jl = ty + it * 8;        // local j within [0, JT)
        const int j  = j0 + jl;            // global j

        F4U c0, c1, c2;
        {
            const size_t cb = (size_t)j * COOR * (FILT / 4);
            c0.f4 = C4[cb + 0 * (FILT / 4)];
            c1.f4 = C4[cb + 1 * (FILT / 4)];
            c2.f4 = C4[cb + 2 * (FILT / 4)];
        }

        #pragma unroll
        for (int i = 0; i < TI; i++) {
            const int sb = (i * JT + jl) * COOR;
            const float d0 = sd[sb + 0];   // warp broadcast
            const float d1 = sd[sb + 1];
            const float d2 = sd[sb + 2];
            const ull dp0 = pack2(d0, d0);
            const ull dp1 = pack2(d1, d1);
            const ull dp2 = pack2(d2, d2);

            const ull a0l = add2(Ar[i][0].u[0], c0.u[0]);
            const ull a0h = add2(Ar[i][0].u[1], c0.u[1]);
            const ull a1l = add2(Ar[i][1].u[0], c1.u[0]);
            const ull a1h = add2(Ar[i][1].u[1], c1.u[1]);
            const ull a2l = add2(Ar[i][2].u[0], c2.u[0]);
            const ull a2h = add2(Ar[i][2].u[1], c2.u[1]);

            F4U o;
            o.u[0] = fma2(a0l, dp0, fma2(a1l, dp1, mul2(a2l, dp2)));
            o.u[1] = fma2(a0h, dp0, fma2(a1h, dp1, mul2(a2h, dp2)));

            out4[((size_t)i * NN + jl) * (FILT / 4)] = o.f4;
        }
    }
}

extern "C" void kernel_launch(void* const* d_in, const int* in_sizes, int n_in,
                              void* d_out, int out_size)
{
    const float* x    = (const float*)d_in[0];  // vector_features [8,128,3,128]
    const float* dist = (const float*)d_in[1];  // distances       [8,128,128,3]
    const float* w    = (const float*)d_in[2];  // w_vs            [256,128]
    const float* bv   = (const float*)d_in[3];  // b_vs            [128]
    float* out = (float*)d_out;                 // [8,128,128,128]

    (void)in_sizes; (void)n_in; (void)out_size;

    phase1_kernel<<<(BB * NN * COOR) / 8, 128>>>(x, w, bv);
    phase2_kernel<<<dim3(NN / 4, 2, BB), dim3(32, 8)>>>(dist, out);
}

// round 4
// speedup vs baseline: 1.1354x; 1.1354x over previous
#include <cuda_runtime.h>

#define BB   8
#define NN   128
#define COOR 3
#define FF   128
#define FILT 128

// Scratch: A' = x @ w1 + bv  and  C = x @ w2, each [B, N, COOR, FILT]
__device__ float g_A[BB * NN * COOR * FILT];
__device__ float g_C[BB * NN * COOR * FILT];

// ---- packed f32x2 helpers (phase 1 only) ----------------------------------
typedef unsigned long long ull;

union F4U {
    float4 f4;
    ull    u[2];
};

__device__ __forceinline__ ull fma2(ull a, ull b, ull c) {
    ull r;
    asm("fma.rn.f32x2 %0, %1, %2, %3;" : "=l"(r) : "l"(a), "l"(b), "l"(c));
    return r;
}
__device__ __forceinline__ ull pack2(float lo, float hi) {
    ull r;
    asm("mov.b64 %0, {%1, %2};" : "=l"(r) : "r"(__float_as_uint(lo)), "r"(__float_as_uint(hi)));
    return r;
}

// ---------------------------------------------------------------------------
// Phase 1: tiny GEMM [3072, 128] @ [128, 256]  ->  g_A (with +bv), g_C
// Block = 128 thr (4 warps), 8 rows/block, 384 blocks. Each lane owns 4 k.
// The w loads for step f+1 are prefetched while step f's FMAs execute, so
// the L1 latency (~39cyc) is hidden even at ~2.6 warps/SMSP.
// ---------------------------------------------------------------------------
__global__ __launch_bounds__(128) void phase1_kernel(
    const float* __restrict__ x,   // [3072, 128]
    const float* __restrict__ w,   // [256, 128]
    const float* __restrict__ bv)  // [128]
{
    constexpr int WR = 2;                 // rows per warp
    constexpr int BR = 8;                 // rows per block
    const int r0   = blockIdx.x * BR;
    const int warp = threadIdx.x >> 5;
    const int lane = threadIdx.x & 31;
    const int k    = lane * 4;
    const int rbase = warp * WR;

    __shared__ float xs[BR][FF];

    {
        const float4* xin = reinterpret_cast<const float4*>(x + (size_t)r0 * FF);
        float4* xs4 = reinterpret_cast<float4*>(&xs[0][0]);
        #pragma unroll
        for (int t = threadIdx.x; t < BR * FF / 4; t += 128) xs4[t] = xin[t];
    }
    __syncthreads();

    ull acc[WR][2][2];   // [row][A/C][pair]
    {
        F4U bvq;
        bvq.f4 = *reinterpret_cast<const float4*>(bv + k);
        #pragma unroll
        for (int r = 0; r < WR; r++) {
            acc[r][0][0] = bvq.u[0];  acc[r][0][1] = bvq.u[1];
            acc[r][1][0] = 0ull;      acc[r][1][1] = 0ull;
        }
    }

    const float4* w1p = reinterpret_cast<const float4*>(w) + lane;
    const float4* w2p = reinterpret_cast<const float4*>(w + (size_t)FF * FILT) + lane;

    // Software pipeline: W holds step f's weights, prefetch f+1 before FMAs.
    F4U W1, W2;
    W1.f4 = w1p[0];
    W2.f4 = w2p[0];

    #pragma unroll 4
    for (int f = 0; f < FF; f++) {
        F4U N1, N2;
        if (f + 1 < FF) {
            N1.f4 = w1p[(f + 1) * (FILT / 4)];
            N2.f4 = w2p[(f + 1) * (FILT / 4)];
        }
        #pragma unroll
        for (int r = 0; r < WR; r++) {
            const float xv = xs[rbase + r][f];     // smem broadcast
            const ull xp = pack2(xv, xv);
            acc[r][0][0] = fma2(xp, W1.u[0], acc[r][0][0]);
            acc[r][0][1] = fma2(xp, W1.u[1], acc[r][0][1]);
            acc[r][1][0] = fma2(xp, W2.u[0], acc[r][1][0]);
            acc[r][1][1] = fma2(xp, W2.u[1], acc[r][1][1]);
        }
        W1 = N1; W2 = N2;
    }

    #pragma unroll
    for (int r = 0; r < WR; r++) {
        const size_t row = (size_t)(r0 + rbase + r);
        F4U oa; oa.u[0] = acc[r][0][0]; oa.u[1] = acc[r][0][1];
        F4U oc; oc.u[0] = acc[r][1][0]; oc.u[1] = acc[r][1][1];
        *reinterpret_cast<float4*>(&g_A[row * FILT + k]) = oa.f4;
        *reinterpret_cast<float4*>(&g_C[row * FILT + k]) = oc.f4;
    }
}

// ---------------------------------------------------------------------------
// Phase 2: out[b,i,j,k] = sum_c (A'[b,i,c,k] + C[b,j,c,k]) * d[b,i,j,c]
// Grid (32, 8) = 256 blocks; block (32,8): tx = k as float4, ty strides j.
// TI=4 i-rows per block; A' in registers; distances PADDED to float4 in smem
// so each (i,j) needs ONE broadcast LDS.128 instead of 3 scalar LDS.
// C loads software-pipelined one j-iteration ahead.
// ---------------------------------------------------------------------------
__global__ __launch_bounds__(256) void phase2_kernel(
    const float* __restrict__ dist,  // [B, N, N, COOR]
    float* __restrict__ out)         // [B, N, N, FILT]
{
    constexpr int TI = 4;
    const int b  = blockIdx.y;
    const int i0 = blockIdx.x * TI;
    const int tx = threadIdx.x;   // 0..31
    const int ty = threadIdx.y;   // 0..7
    const int tid = ty * 32 + tx;

    __shared__ float4 sd4[TI * NN];   // padded (d0,d1,d2,_) per (i,j): 8 KB

    // Load + pad distances slice d[b, i0:i0+4, :, :].
    {
        const float* dbase = dist + (size_t)(b * NN + i0) * NN * COOR;
        #pragma unroll
        for (int t = tid; t < TI * NN; t += 256) {
            const int e = t * COOR;
            sd4[t] = make_float4(dbase[e], dbase[e + 1], dbase[e + 2], 0.0f);
        }
    }

    // A' tile into registers: 4 i x 3 c x float4 = 48 regs.
    float4 Ar[TI][COOR];
    {
        const float4* A4 = reinterpret_cast<const float4*>(g_A);
        #pragma unroll
        for (int i = 0; i < TI; i++)
            #pragma unroll
            for (int c = 0; c < COOR; c++)
                Ar[i][c] = A4[((size_t)(b * NN + i0 + i) * COOR + c) * (FILT / 4) + tx];
    }
    __syncthreads();

    const float4* C4 = reinterpret_cast<const float4*>(g_C) +
                       (size_t)b * NN * COOR * (FILT / 4) + tx;
    float4* out4 = reinterpret_cast<float4*>(out) +
                   ((size_t)(b * NN + i0) * NN) * (FILT / 4) + tx;

    // Prime pipeline with j = ty.
    float4 c0 = C4[(size_t)ty * COOR * (FILT / 4) + 0 * (FILT / 4)];
    float4 c1 = C4[(size_t)ty * COOR * (FILT / 4) + 1 * (FILT / 4)];
    float4 c2 = C4[(size_t)ty * COOR * (FILT / 4) + 2 * (FILT / 4)];

    #pragma unroll
    for (int it = 0; it < NN / 8; it++) {
        const int j = ty + it * 8;

        float4 n0, n1, n2;
        if (it + 1 < NN / 8) {
            const size_t nb = (size_t)(j + 8) * COOR * (FILT / 4);
            n0 = C4[nb + 0 * (FILT / 4)];
            n1 = C4[nb + 1 * (FILT / 4)];
            n2 = C4[nb + 2 * (FILT / 4)];
        }

        #pragma unroll
        for (int i = 0; i < TI; i++) {
            const float4 dv = sd4[i * NN + j];   // one LDS.128, broadcast
            const float d0 = dv.x, d1 = dv.y, d2 = dv.z;

            float4 o;
            o.x = fmaf(Ar[i][0].x + c0.x, d0,
                  fmaf(Ar[i][1].x + c1.x, d1, (Ar[i][2].x + c2.x) * d2));
            o.y = fmaf(Ar[i][0].y + c0.y, d0,
                  fmaf(Ar[i][1].y + c1.y, d1, (Ar[i][2].y + c2.y) * d2));
            o.z = fmaf(Ar[i][0].z + c0.z, d0,
                  fmaf(Ar[i][1].z + c1.z, d1, (Ar[i][2].z + c2.z) * d2));
            o.w = fmaf(Ar[i][0].w + c0.w, d0,
                  fmaf(Ar[i][1].w + c1.w, d1, (Ar[i][2].w + c2.w) * d2));

            out4[((size_t)i * NN + j) * (FILT / 4)] = o;
        }

        c0 = n0; c1 = n1; c2 = n2;
    }
}

extern "C" void kernel_launch(void* const* d_in, const int* in_sizes, int n_in,
                              void* d_out, int out_size)
{
    const float* x    = (const float*)d_in[0];  // vector_features [8,128,3,128]
    const float* dist = (const float*)d_in[1];  // distances       [8,128,128,3]
    const float* w    = (const float*)d_in[2];  // w_vs            [256,128]
    const float* bv   = (const float*)d_in[3];  // b_vs            [128]
    float* out = (float*)d_out;                 // [8,128,128,128]

    (void)in_sizes; (void)n_in; (void)out_size;

    phase1_kernel<<<(BB * NN * COOR) / 8, 128>>>(x, w, bv);
    phase2_kernel<<<dim3(NN / 4, BB), dim3(32, 8)>>>(dist, out);
}